// round 1
// baseline (speedup 1.0000x reference)
#include <cuda_runtime.h>
#include <math.h>

// Problem constants
#define NB 16
#define LL 512
#define HH 1024
#define HD 64
#define NHEADS 12
#define BL (NB * LL)       // 8192 rows
#define INF_VAL 1.0e12f

// Scratch (device globals — no allocations allowed)
static __device__ float g_x[BL * 128];          // x = inputs@W1 + b1   (4 MB)
static __device__ float g_q[BL * 64];           // rope'd qw            (2 MB)
static __device__ float g_k[BL * 64];           // rope'd kw            (2 MB)
static __device__ float g_bA[NB * NHEADS * LL]; // bias even heads (added along n)
static __device__ float g_bB[NB * NHEADS * LL]; // bias odd heads  (added along m)

// Packed f32x2 FMA (2 FMAs per instruction; ptxas won't auto-fuse, PTX only)
#define FMA2(d, a, b, c) \
    asm("fma.rn.f32x2 %0, %1, %2, %3;" : "=l"(d) : "l"(a), "l"(b), "l"(c))
#define PACKDUP(d, v) \
    asm("mov.b64 %0, {%1, %1};" : "=l"(d) : "f"(v))
#define UNPACK2(lo, hi, d) \
    asm("mov.b64 {%0, %1}, %2;" : "=f"(lo), "=f"(hi) : "l"(d))

// ---------------------------------------------------------------------------
// Kernel 1: x[8192,128] = inputs[8192,1024] @ W1[1024,128] + b1
// Tile: BM=32, BN=128 (full), BK=32. 256 blocks x 128 threads.
// Each thread: 4 rows x 8 cols, accumulated as 4x4 packed f32x2.
// ---------------------------------------------------------------------------
__global__ __launch_bounds__(128) void gemm1_kernel(const float* __restrict__ A,
                                                    const float* __restrict__ W1,
                                                    const float* __restrict__ b1) {
    __shared__ float Ast[32][36];   // [k][m], padded (36: 16B-aligned rows, spread banks)
    __shared__ float Bs[32][128];   // [k][n]

    const int tid = threadIdx.x;
    const int m0  = blockIdx.x * 32;
    const int tx  = tid & 15;
    const int ty  = tid >> 4;
    const int c0  = tx * 8;   // output column base (8 cols)
    const int r0  = ty * 4;   // output row base (4 rows)

    unsigned long long acc[4][4];
#pragma unroll
    for (int i = 0; i < 4; i++)
#pragma unroll
        for (int p = 0; p < 4; p++) acc[i][p] = 0ULL;

    for (int kt = 0; kt < 1024; kt += 32) {
        // Load A tile (32 rows x 32 k) transposed into Ast[k][m]
#pragma unroll
        for (int it = 0; it < 2; it++) {
            int idx = tid + it * 128;
            int r   = idx >> 3;
            int kc  = (idx & 7) * 4;
            float4 av = *(const float4*)&A[(size_t)(m0 + r) * 1024 + kt + kc];
            Ast[kc + 0][r] = av.x;
            Ast[kc + 1][r] = av.y;
            Ast[kc + 2][r] = av.z;
            Ast[kc + 3][r] = av.w;
        }
        // Load B tile (32 k x 128 n)
#pragma unroll
        for (int it = 0; it < 8; it++) {
            int idx = tid + it * 128;
            int kr  = idx >> 5;
            int cc  = (idx & 31) * 4;
            *(float4*)&Bs[kr][cc] = *(const float4*)&W1[(size_t)(kt + kr) * 128 + cc];
        }
        __syncthreads();

#pragma unroll
        for (int kk = 0; kk < 32; kk++) {
            float4 a4 = *(const float4*)&Ast[kk][r0];
            ulonglong2 b01 = *(const ulonglong2*)&Bs[kk][c0];
            ulonglong2 b23 = *(const ulonglong2*)&Bs[kk][c0 + 4];
            unsigned long long ad0, ad1, ad2, ad3;
            PACKDUP(ad0, a4.x);
            PACKDUP(ad1, a4.y);
            PACKDUP(ad2, a4.z);
            PACKDUP(ad3, a4.w);
            FMA2(acc[0][0], ad0, b01.x, acc[0][0]);
            FMA2(acc[0][1], ad0, b01.y, acc[0][1]);
            FMA2(acc[0][2], ad0, b23.x, acc[0][2]);
            FMA2(acc[0][3], ad0, b23.y, acc[0][3]);
            FMA2(acc[1][0], ad1, b01.x, acc[1][0]);
            FMA2(acc[1][1], ad1, b01.y, acc[1][1]);
            FMA2(acc[1][2], ad1, b23.x, acc[1][2]);
            FMA2(acc[1][3], ad1, b23.y, acc[1][3]);
            FMA2(acc[2][0], ad2, b01.x, acc[2][0]);
            FMA2(acc[2][1], ad2, b01.y, acc[2][1]);
            FMA2(acc[2][2], ad2, b23.x, acc[2][2]);
            FMA2(acc[2][3], ad2, b23.y, acc[2][3]);
            FMA2(acc[3][0], ad3, b01.x, acc[3][0]);
            FMA2(acc[3][1], ad3, b01.y, acc[3][1]);
            FMA2(acc[3][2], ad3, b23.x, acc[3][2]);
            FMA2(acc[3][3], ad3, b23.y, acc[3][3]);
        }
        __syncthreads();
    }

    // Epilogue: + b1, store to g_x
    float bv[8];
#pragma unroll
    for (int j = 0; j < 8; j++) bv[j] = b1[c0 + j];
#pragma unroll
    for (int i = 0; i < 4; i++) {
        float o[8];
        UNPACK2(o[0], o[1], acc[i][0]);
        UNPACK2(o[2], o[3], acc[i][1]);
        UNPACK2(o[4], o[5], acc[i][2]);
        UNPACK2(o[6], o[7], acc[i][3]);
        float4 s0 = make_float4(o[0] + bv[0], o[1] + bv[1], o[2] + bv[2], o[3] + bv[3]);
        float4 s1 = make_float4(o[4] + bv[4], o[5] + bv[5], o[6] + bv[6], o[7] + bv[7]);
        size_t base = (size_t)(m0 + r0 + i) * 128 + c0;
        *(float4*)&g_x[base]     = s0;
        *(float4*)&g_x[base + 4] = s1;
    }
}

// ---------------------------------------------------------------------------
// Kernel 2: per (b,l) row — rope qw/kw, bias24 = (x@W2 + b2)/2 split into bA/bB.
// One warp per row. 1024 blocks x 256 threads (8 warps = 8 rows / block).
// Lane i owns x[4i..4i+3] = (qw[2i], kw[2i], qw[2i+1], kw[2i+1]) — the rope pair.
// ---------------------------------------------------------------------------
__global__ __launch_bounds__(256) void prep_kernel(const float* __restrict__ W2,
                                                   const float* __restrict__ b2) {
    __shared__ float W2s[128 * 24];
    const int tid = threadIdx.x;
    for (int idx = tid; idx < 128 * 24; idx += 256) W2s[idx] = W2[idx];
    __syncthreads();

    const int lane = tid & 31;
    const int row  = blockIdx.x * 8 + (tid >> 5);
    const int b    = row >> 9;
    const int l    = row & 511;

    float4 xv = *(const float4*)&g_x[(size_t)row * 128 + lane * 4];

    // partial bias dot: this lane's 4 k-positions
    float acc[24];
    const float* w0 = &W2s[(lane * 4 + 0) * 24];
    const float* w1 = &W2s[(lane * 4 + 1) * 24];
    const float* w2 = &W2s[(lane * 4 + 2) * 24];
    const float* w3 = &W2s[(lane * 4 + 3) * 24];
#pragma unroll
    for (int c = 0; c < 24; c++)
        acc[c] = xv.x * w0[c] + xv.y * w1[c] + xv.z * w2[c] + xv.w * w3[c];

    // warp reduce all 24 channels
#pragma unroll
    for (int c = 0; c < 24; c++) {
#pragma unroll
        for (int o = 16; o > 0; o >>= 1)
            acc[c] += __shfl_xor_sync(0xffffffffu, acc[c], o);
    }
    if (lane == 0) {
#pragma unroll
        for (int h = 0; h < NHEADS; h++) {
            g_bA[((size_t)b * NHEADS + h) * LL + l] = 0.5f * (acc[2 * h]     + b2[2 * h]);
            g_bB[((size_t)b * NHEADS + h) * LL + l] = 0.5f * (acc[2 * h + 1] + b2[2 * h + 1]);
        }
    }

    // rope: pair index i = lane, inv_freq = 10000^(-i/32)
    float invf = (float)pow(10000.0, -(double)lane * (1.0 / 32.0));
    float ph = (float)l * invf;
    float s, cs;
    sincosf(ph, &s, &cs);
    float2 qo, ko;
    qo.x = xv.x * cs - xv.z * s;    // qw[2i]
    qo.y = xv.x * s  + xv.z * cs;   // qw[2i+1]
    ko.x = xv.y * cs - xv.w * s;    // kw[2i]
    ko.y = xv.y * s  + xv.w * cs;   // kw[2i+1]
    *(float2*)&g_q[(size_t)row * 64 + lane * 2] = qo;
    *(float2*)&g_k[(size_t)row * 64 + lane * 2] = ko;
}

// ---------------------------------------------------------------------------
// Kernel 3: out[b,h,m,n] = s(m,n)/8 + bA[b,h,n] + bB[b,h,m] - masks
// s tile 64x64 per block; 12 heads expanded from the same s tile (write-bound).
// Grid (L/64, L/64, B) = (8,8,16); 256 threads; 4x4 micro-tile per thread.
// ---------------------------------------------------------------------------
__global__ __launch_bounds__(256) void logits_kernel(const float* __restrict__ amask,
                                                     float* __restrict__ out) {
    __shared__ float qs[64][68];
    __shared__ float ks[64][68];
    __shared__ float bAs[12][64];
    __shared__ float bBs[12][64];
    __shared__ float amM[64];
    __shared__ float amN[64];

    const int tid = threadIdx.x;
    const int n0 = blockIdx.x * 64;
    const int m0 = blockIdx.y * 64;
    const int b  = blockIdx.z;
    const size_t rb = (size_t)b * LL;

#pragma unroll
    for (int it = 0; it < 4; it++) {
        int idx = tid + it * 256;
        int r   = idx >> 4;
        int cc  = (idx & 15) * 4;
        *(float4*)&qs[r][cc] = *(const float4*)&g_q[(rb + m0 + r) * 64 + cc];
        *(float4*)&ks[r][cc] = *(const float4*)&g_k[(rb + n0 + r) * 64 + cc];
    }
#pragma unroll
    for (int it = 0; it < 3; it++) {
        int idx = tid + it * 256;
        int h   = idx >> 6;
        int p   = idx & 63;
        bAs[h][p] = g_bA[((size_t)b * NHEADS + h) * LL + n0 + p];
        bBs[h][p] = g_bB[((size_t)b * NHEADS + h) * LL + m0 + p];
    }
    if (tid < 64)       amM[tid]      = amask[rb + m0 + tid];
    else if (tid < 128) amN[tid - 64] = amask[rb + n0 + (tid - 64)];
    __syncthreads();

    const int tx = tid & 15;
    const int ty = tid >> 4;
    const int c0 = tx * 4;
    const int r0 = ty * 4;

    float acc[4][4] = {};
#pragma unroll
    for (int d = 0; d < 64; d += 4) {
        float4 q[4], k[4];
#pragma unroll
        for (int i = 0; i < 4; i++) q[i] = *(const float4*)&qs[r0 + i][d];
#pragma unroll
        for (int j = 0; j < 4; j++) k[j] = *(const float4*)&ks[c0 + j][d];
#pragma unroll
        for (int i = 0; i < 4; i++)
#pragma unroll
            for (int j = 0; j < 4; j++)
                acc[i][j] += q[i].x * k[j].x + q[i].y * k[j].y +
                             q[i].z * k[j].z + q[i].w * k[j].w;
    }

    // scale + masks folded into base tile
    float base[4][4];
#pragma unroll
    for (int i = 0; i < 4; i++) {
        int m = m0 + r0 + i;
        float amm = amM[r0 + i];
#pragma unroll
        for (int j = 0; j < 4; j++) {
            int n = n0 + c0 + j;
            float msk = (1.0f - amm * amN[c0 + j]) * INF_VAL;
            if (n < m) msk += INF_VAL;           // tril(k=-1)
            base[i][j] = acc[i][j] * 0.125f - msk;   // / sqrt(64)
        }
    }

    const size_t ob = (size_t)b * NHEADS * LL * LL;
#pragma unroll
    for (int h = 0; h < NHEADS; h++) {
        float4 bA = *(const float4*)&bAs[h][c0];
#pragma unroll
        for (int i = 0; i < 4; i++) {
            float bB = bBs[h][r0 + i];
            float4 v;
            v.x = base[i][0] + bA.x + bB;
            v.y = base[i][1] + bA.y + bB;
            v.z = base[i][2] + bA.z + bB;
            v.w = base[i][3] + bA.w + bB;
            *(float4*)&out[ob + ((size_t)h * LL + (m0 + r0 + i)) * LL + n0 + c0] = v;
        }
    }
}

// ---------------------------------------------------------------------------
extern "C" void kernel_launch(void* const* d_in, const int* in_sizes, int n_in,
                              void* d_out, int out_size) {
    (void)in_sizes; (void)n_in; (void)out_size;
    const float* inputs = (const float*)d_in[0];
    const float* amask  = (const float*)d_in[1];
    const float* W1     = (const float*)d_in[2];
    const float* b1     = (const float*)d_in[3];
    const float* W2     = (const float*)d_in[4];
    const float* b2     = (const float*)d_in[5];
    float* out = (float*)d_out;

    gemm1_kernel<<<BL / 32, 128>>>(inputs, W1, b1);
    prep_kernel<<<BL / 8, 256>>>(W2, b2);
    logits_kernel<<<dim3(LL / 64, LL / 64, NB), 256>>>(amask, out);
}

// round 5
// speedup vs baseline: 1.2036x; 1.2036x over previous
#include <cuda_runtime.h>
#include <math.h>

// Problem constants
#define NB 16
#define LL 512
#define HH 1024
#define HD 64
#define NHEADS 12
#define BL (NB * LL)       // 8192 rows
#define INF_VAL 1.0e12f

// Scratch (device globals — no allocations allowed)
static __device__ float g_x[BL * 128];          // x = inputs@W1 + b1   (4 MB)
static __device__ float g_q[BL * 64];           // rope'd qw            (2 MB)
static __device__ float g_k[BL * 64];           // rope'd kw            (2 MB)
static __device__ float g_bA[NB * NHEADS * LL]; // bias even heads (added along n)
static __device__ float g_bB[NB * NHEADS * LL]; // bias odd heads  (added along m)

// Packed f32x2 FMA (2 FMAs per instruction; ptxas won't auto-fuse, PTX only)
#define FMA2(d, a, b, c) \
    asm("fma.rn.f32x2 %0, %1, %2, %3;" : "=l"(d) : "l"(a), "l"(b), "l"(c))
#define UNPACK2(lo, hi, d) \
    asm("mov.b64 {%0, %1}, %2;" : "=f"(lo), "=f"(hi) : "l"(d))

// ---------------------------------------------------------------------------
// Kernel 1: x[8192,128] = inputs[8192,1024] @ W1[1024,128] + b1
// BM=32, BN=128, BK=32. 256 CTAs x 256 threads. Micro-tile 4 rows x 4 cols.
// Column pairs packed as f32x2; A duplicated in smem so inner loop is
// 3 LDS.128 + 8 FMA2 per k. Register-staged double buffering.
// ---------------------------------------------------------------------------
__global__ __launch_bounds__(256) void gemm1_kernel(const float* __restrict__ A,
                                                    const float* __restrict__ W1,
                                                    const float* __restrict__ b1) {
    // A stored duplicated: Ad[k][2m] = Ad[k][2m+1] = A(m, k). Row width 68 floats
    // (pad: float4-aligned reads at 8*ty, 4-way-max conflicted dup stores).
    __shared__ float Ad[2][32][68];
    __shared__ float Bs[2][32][128];

    const int tid = threadIdx.x;
    const int m0  = blockIdx.x * 32;
    const int tx  = tid & 31;        // col group: c0 = 4*tx
    const int ty  = tid >> 5;        // row group: r0 = 4*ty (all lanes of a warp share ty)
    const int c0  = tx * 4;
    const int r0  = ty * 4;

    // loader indices
    const int ar = tid >> 3;         // A row 0..31
    const int ak = (tid & 7) * 4;    // A k-offset 0..28

    unsigned long long acc[4][2];
#pragma unroll
    for (int i = 0; i < 4; i++) { acc[i][0] = 0ULL; acc[i][1] = 0ULL; }

    // ---- prologue: load tile 0 into buffer 0
    {
        float4 av = *(const float4*)&A[(size_t)(m0 + ar) * 1024 + ak];
        *(float2*)&Ad[0][ak + 0][2 * ar] = make_float2(av.x, av.x);
        *(float2*)&Ad[0][ak + 1][2 * ar] = make_float2(av.y, av.y);
        *(float2*)&Ad[0][ak + 2][2 * ar] = make_float2(av.z, av.z);
        *(float2*)&Ad[0][ak + 3][2 * ar] = make_float2(av.w, av.w);
#pragma unroll
        for (int it = 0; it < 4; it++) {
            int idx = tid + it * 256;
            int kr  = idx >> 5;
            int cc  = (idx & 31) * 4;
            *(float4*)&Bs[0][kr][cc] = *(const float4*)&W1[(size_t)kr * 128 + cc];
        }
    }
    __syncthreads();

    int s = 0;
    for (int kt = 0; kt < 1024; kt += 32) {
        // prefetch next tile into registers
        float4 apre;
        float4 bpre[4];
        const bool more = (kt + 32) < 1024;
        if (more) {
            apre = *(const float4*)&A[(size_t)(m0 + ar) * 1024 + kt + 32 + ak];
#pragma unroll
            for (int it = 0; it < 4; it++) {
                int idx = tid + it * 256;
                int kr  = idx >> 5;
                int cc  = (idx & 31) * 4;
                bpre[it] = *(const float4*)&W1[(size_t)(kt + 32 + kr) * 128 + cc];
            }
        }

        // compute current tile
#pragma unroll
        for (int kk = 0; kk < 32; kk++) {
            ulonglong2 a01 = *(const ulonglong2*)&Ad[s][kk][2 * r0];      // rows r0, r0+1 (dup)
            ulonglong2 a23 = *(const ulonglong2*)&Ad[s][kk][2 * r0 + 4];  // rows r0+2, r0+3
            ulonglong2 b   = *(const ulonglong2*)&Bs[s][kk][c0];          // 2 packed col-pairs
            FMA2(acc[0][0], a01.x, b.x, acc[0][0]);
            FMA2(acc[0][1], a01.x, b.y, acc[0][1]);
            FMA2(acc[1][0], a01.y, b.x, acc[1][0]);
            FMA2(acc[1][1], a01.y, b.y, acc[1][1]);
            FMA2(acc[2][0], a23.x, b.x, acc[2][0]);
            FMA2(acc[2][1], a23.x, b.y, acc[2][1]);
            FMA2(acc[3][0], a23.y, b.x, acc[3][0]);
            FMA2(acc[3][1], a23.y, b.y, acc[3][1]);
        }

        if (more) {
            int d = s ^ 1;
            *(float2*)&Ad[d][ak + 0][2 * ar] = make_float2(apre.x, apre.x);
            *(float2*)&Ad[d][ak + 1][2 * ar] = make_float2(apre.y, apre.y);
            *(float2*)&Ad[d][ak + 2][2 * ar] = make_float2(apre.z, apre.z);
            *(float2*)&Ad[d][ak + 3][2 * ar] = make_float2(apre.w, apre.w);
#pragma unroll
            for (int it = 0; it < 4; it++) {
                int idx = tid + it * 256;
                int kr  = idx >> 5;
                int cc  = (idx & 31) * 4;
                *(float4*)&Bs[d][kr][cc] = bpre[it];
            }
        }
        __syncthreads();
        s ^= 1;
    }

    // epilogue: + b1, store to g_x
    float4 bv = *(const float4*)&b1[c0];
#pragma unroll
    for (int i = 0; i < 4; i++) {
        float o0, o1, o2, o3;
        UNPACK2(o0, o1, acc[i][0]);
        UNPACK2(o2, o3, acc[i][1]);
        float4 v = make_float4(o0 + bv.x, o1 + bv.y, o2 + bv.z, o3 + bv.w);
        *(float4*)&g_x[(size_t)(m0 + r0 + i) * 128 + c0] = v;
    }
}

// ---------------------------------------------------------------------------
// Kernel 2: per (b,l) row — rope qw/kw, bias24 = (x@W2 + b2)/2 split into bA/bB.
// One warp per row. 1024 blocks x 256 threads (8 warps = 8 rows / block).
// Lane i owns x[4i..4i+3] = (qw[2i], kw[2i], qw[2i+1], kw[2i+1]).
// ---------------------------------------------------------------------------
__global__ __launch_bounds__(256) void prep_kernel(const float* __restrict__ W2,
                                                   const float* __restrict__ b2) {
    __shared__ float W2s[128 * 24];
    const int tid = threadIdx.x;
    for (int idx = tid; idx < 128 * 24; idx += 256) W2s[idx] = W2[idx];
    __syncthreads();

    const int lane = tid & 31;
    const int row  = blockIdx.x * 8 + (tid >> 5);
    const int b    = row >> 9;
    const int l    = row & 511;

    float4 xv = *(const float4*)&g_x[(size_t)row * 128 + lane * 4];

    float acc[24];
    const float* w0 = &W2s[(lane * 4 + 0) * 24];
    const float* w1 = &W2s[(lane * 4 + 1) * 24];
    const float* w2 = &W2s[(lane * 4 + 2) * 24];
    const float* w3 = &W2s[(lane * 4 + 3) * 24];
#pragma unroll
    for (int c = 0; c < 24; c++)
        acc[c] = xv.x * w0[c] + xv.y * w1[c] + xv.z * w2[c] + xv.w * w3[c];

#pragma unroll
    for (int c = 0; c < 24; c++) {
#pragma unroll
        for (int o = 16; o > 0; o >>= 1)
            acc[c] += __shfl_xor_sync(0xffffffffu, acc[c], o);
    }
    if (lane == 0) {
#pragma unroll
        for (int h = 0; h < NHEADS; h++) {
            g_bA[((size_t)b * NHEADS + h) * LL + l] = 0.5f * (acc[2 * h]     + b2[2 * h]);
            g_bB[((size_t)b * NHEADS + h) * LL + l] = 0.5f * (acc[2 * h + 1] + b2[2 * h + 1]);
        }
    }

    float invf = (float)pow(10000.0, -(double)lane * (1.0 / 32.0));
    float ph = (float)l * invf;
    float sn, cs;
    sincosf(ph, &sn, &cs);
    float2 qo, ko;
    qo.x = xv.x * cs - xv.z * sn;
    qo.y = xv.x * sn + xv.z * cs;
    ko.x = xv.y * cs - xv.w * sn;
    ko.y = xv.y * sn + xv.w * cs;
    *(float2*)&g_q[(size_t)row * 64 + lane * 2] = qo;
    *(float2*)&g_k[(size_t)row * 64 + lane * 2] = ko;
}

// ---------------------------------------------------------------------------
// Kernel 3: out[b,h,m,n] = s(m,n)/8 + bA[b,h,n] + bB[b,h,m] - masks
// K stored TRANSPOSED in smem (kst[d][n]) -> conflict-free dot-loop loads.
// Grid (8,8,16); 256 threads; 4x4 micro-tile; 12 heads expanded per tile.
// ---------------------------------------------------------------------------
__global__ __launch_bounds__(256) void logits_kernel(const float* __restrict__ amask,
                                                     float* __restrict__ out) {
    __shared__ float qs[64][68];    // [m][d]
    __shared__ float kst[64][68];   // [d][n]  (transposed)
    __shared__ float bAs[12][64];
    __shared__ float bBs[12][64];
    __shared__ float amM[64];
    __shared__ float amN[64];

    const int tid = threadIdx.x;
    const int n0 = blockIdx.x * 64;
    const int m0 = blockIdx.y * 64;
    const int b  = blockIdx.z;
    const size_t rb = (size_t)b * LL;

#pragma unroll
    for (int it = 0; it < 4; it++) {
        int idx = tid + it * 256;
        int r   = idx >> 4;
        int cc  = (idx & 15) * 4;
        *(float4*)&qs[r][cc] = *(const float4*)&g_q[(rb + m0 + r) * 64 + cc];
        float4 kv = *(const float4*)&g_k[(rb + n0 + r) * 64 + cc];
        kst[cc + 0][r] = kv.x;
        kst[cc + 1][r] = kv.y;
        kst[cc + 2][r] = kv.z;
        kst[cc + 3][r] = kv.w;
    }
#pragma unroll
    for (int it = 0; it < 3; it++) {
        int idx = tid + it * 256;
        int h   = idx >> 6;
        int p   = idx & 63;
        bAs[h][p] = g_bA[((size_t)b * NHEADS + h) * LL + n0 + p];
        bBs[h][p] = g_bB[((size_t)b * NHEADS + h) * LL + m0 + p];
    }
    if (tid < 64)       amM[tid]      = amask[rb + m0 + tid];
    else if (tid < 128) amN[tid - 64] = amask[rb + n0 + (tid - 64)];
    __syncthreads();

    const int tx = tid & 15;
    const int ty = tid >> 4;
    const int c0 = tx * 4;
    const int r0 = ty * 4;

    float acc[4][4] = {};
#pragma unroll
    for (int d4 = 0; d4 < 64; d4 += 4) {
        float4 q[4], kt[4];
#pragma unroll
        for (int i = 0; i < 4; i++) q[i] = *(const float4*)&qs[r0 + i][d4];      // broadcast
#pragma unroll
        for (int dd = 0; dd < 4; dd++) kt[dd] = *(const float4*)&kst[d4 + dd][c0]; // conflict-free
#pragma unroll
        for (int i = 0; i < 4; i++) {
            acc[i][0] += q[i].x * kt[0].x + q[i].y * kt[1].x + q[i].z * kt[2].x + q[i].w * kt[3].x;
            acc[i][1] += q[i].x * kt[0].y + q[i].y * kt[1].y + q[i].z * kt[2].y + q[i].w * kt[3].y;
            acc[i][2] += q[i].x * kt[0].z + q[i].y * kt[1].z + q[i].z * kt[2].z + q[i].w * kt[3].z;
            acc[i][3] += q[i].x * kt[0].w + q[i].y * kt[1].w + q[i].z * kt[2].w + q[i].w * kt[3].w;
        }
    }

    // scale + masks folded into base tile
    float base[4][4];
#pragma unroll
    for (int i = 0; i < 4; i++) {
        int m = m0 + r0 + i;
        float amm = amM[r0 + i];
#pragma unroll
        for (int j = 0; j < 4; j++) {
            int n = n0 + c0 + j;
            float msk = (1.0f - amm * amN[c0 + j]) * INF_VAL;
            if (n < m) msk += INF_VAL;               // tril(k=-1)
            base[i][j] = acc[i][j] * 0.125f - msk;   // / sqrt(64)
        }
    }

    const size_t ob = (size_t)b * NHEADS * LL * LL;
#pragma unroll
    for (int h = 0; h < NHEADS; h++) {
        float4 bA = *(const float4*)&bAs[h][c0];
#pragma unroll
        for (int i = 0; i < 4; i++) {
            float bB = bBs[h][r0 + i];
            float4 v;
            v.x = base[i][0] + bA.x + bB;
            v.y = base[i][1] + bA.y + bB;
            v.z = base[i][2] + bA.z + bB;
            v.w = base[i][3] + bA.w + bB;
            *(float4*)&out[ob + ((size_t)h * LL + (m0 + r0 + i)) * LL + n0 + c0] = v;
        }
    }
}

// ---------------------------------------------------------------------------
extern "C" void kernel_launch(void* const* d_in, const int* in_sizes, int n_in,
                              void* d_out, int out_size) {
    (void)in_sizes; (void)n_in; (void)out_size;
    const float* inputs = (const float*)d_in[0];
    const float* amask  = (const float*)d_in[1];
    const float* W1     = (const float*)d_in[2];
    const float* b1     = (const float*)d_in[3];
    const float* W2     = (const float*)d_in[4];
    const float* b2     = (const float*)d_in[5];
    float* out = (float*)d_out;

    gemm1_kernel<<<BL / 32, 256>>>(inputs, W1, b1);
    prep_kernel<<<BL / 8, 256>>>(W2, b2);
    logits_kernel<<<dim3(LL / 64, LL / 64, NB), 256>>>(amask, out);
}